// round 1
// baseline (speedup 1.0000x reference)
#include <cuda_runtime.h>
#include <math.h>

#define LOG100 4.605170185988092f

// Layout constants
// B=32, H=W=64, C=60, NH=6, HD=10, WS=7, T=49 tokens/window
// padded 70x70 -> nw=10 -> 100 windows/image -> 3200 windows total

__global__ __launch_bounds__(256, 2) void swin_win_attn_kernel(
    const float* __restrict__ x,       // [32,64,64,60]
    const float* __restrict__ qkv_w,   // [180,60]
    const float* __restrict__ qkv_b,   // [180]
    const float* __restrict__ ls,      // [6]
    const float* __restrict__ proj_w,  // [60,60]
    const float* __restrict__ proj_b,  // [60]
    float* __restrict__ out)           // [32,64,64,60]
{
    extern __shared__ float smem[];
    float* Wsm = smem;            // 10800 floats: qkv_w staged
    float* Xs  = smem + 10800;    // 2940 floats: x window, later S (49x49=2401)
    float* QKV = smem + 13740;    // 8820 floats: q|k|v each [6][49][10]; later proj_w (3600)
    float* Osm = smem + 22560;    // 2940 floats: attention output [49][60]

    const int tid = threadIdx.x;
    const int w  = blockIdx.x;
    const int b  = w / 100;
    const int wi = (w % 100) / 10;
    const int wj = w % 10;

    // ---- stage qkv_w into smem (vectorized) ----
    {
        const float4* wg4 = (const float4*)qkv_w;
        float4* ws4 = (float4*)Wsm;
        for (int i = tid; i < 2700; i += 256) ws4[i] = wg4[i];
    }

    // ---- load x window with zero padding ----
    for (int l = tid; l < 2940; l += 256) {
        int t = l / 60, c = l % 60;
        int r  = wi * 7 + t / 7;
        int cc = wj * 7 + t % 7;
        Xs[l] = (r < 64 && cc < 64) ? x[((b * 64 + r) * 64 + cc) * 60 + c] : 0.0f;
    }
    __syncthreads();

    // ---- QKV projection: 49 tokens x 180 outputs, K=60 ----
    // thread tile: 7 tokens x 5 outputs (252 active threads)
    if (tid < 252) {
        const int tg = tid % 7, og = tid / 7;
        const int t0 = tg * 7, o0 = og * 5;
        float acc[7][5];
        #pragma unroll
        for (int j = 0; j < 5; j++) {
            float bv = __ldg(qkv_b + o0 + j);
            #pragma unroll
            for (int i = 0; i < 7; i++) acc[i][j] = bv;
        }
        #pragma unroll
        for (int c4 = 0; c4 < 15; c4++) {
            float4 xv[7];
            #pragma unroll
            for (int i = 0; i < 7; i++)
                xv[i] = *(const float4*)&Xs[(t0 + i) * 60 + c4 * 4];
            #pragma unroll
            for (int j = 0; j < 5; j++) {
                float4 wv = *(const float4*)&Wsm[(o0 + j) * 60 + c4 * 4];
                #pragma unroll
                for (int i = 0; i < 7; i++) {
                    acc[i][j] = fmaf(xv[i].x, wv.x, acc[i][j]);
                    acc[i][j] = fmaf(xv[i].y, wv.y, acc[i][j]);
                    acc[i][j] = fmaf(xv[i].z, wv.z, acc[i][j]);
                    acc[i][j] = fmaf(xv[i].w, wv.w, acc[i][j]);
                }
            }
        }
        // scatter into q|k|v [part][h][t][d]
        #pragma unroll
        for (int j = 0; j < 5; j++) {
            int o = o0 + j;
            int part = o / 60, hh = (o % 60) / 10, d = o % 10;
            float* dst = QKV + part * 2940 + hh * 490 + d;
            #pragma unroll
            for (int i = 0; i < 7; i++) dst[(t0 + i) * 10] = acc[i][j];
        }
    }
    __syncthreads();

    // ---- normalize q (with folded logit scale) and k ----
    for (int idx = tid; idx < 588; idx += 256) {
        int part = idx / 294;           // 0=q, 1=k
        int rem = idx % 294;
        int h = rem / 49, t = rem % 49;
        float* p = QKV + part * 2940 + h * 490 + t * 10;
        float ss = 0.0f;
        #pragma unroll
        for (int d = 0; d < 10; d++) ss = fmaf(p[d], p[d], ss);
        float inv = 1.0f / fmaxf(sqrtf(ss), 1e-12f);
        if (part == 0) inv *= expf(fminf(__ldg(ls + h), LOG100));
        #pragma unroll
        for (int d = 0; d < 10; d++) p[d] *= inv;
    }
    __syncthreads();

    // ---- attention, per head ----
    float* S = Xs;                      // 49x49 scores
    const int lane = tid & 31, warp = tid >> 5;
    for (int h = 0; h < 6; h++) {
        const float* qh = QKV + h * 490;
        const float* kh = QKV + 2940 + h * 490;
        const float* vh = QKV + 5880 + h * 490;

        // scores: thread = (qi, kj-stripe)
        if (tid < 245) {
            int qi = tid / 5, j0 = tid % 5;
            float2 qr[5];
            #pragma unroll
            for (int d = 0; d < 5; d++)
                qr[d] = *(const float2*)&qh[qi * 10 + d * 2];
            for (int kj = j0; kj < 49; kj += 5) {
                float s = 0.0f;
                #pragma unroll
                for (int d = 0; d < 5; d++) {
                    float2 kr = *(const float2*)&kh[kj * 10 + d * 2];
                    s = fmaf(qr[d].x, kr.x, s);
                    s = fmaf(qr[d].y, kr.y, s);
                }
                S[qi * 49 + kj] = s;
            }
        }
        __syncthreads();

        // softmax: warp per row
        for (int r = warp; r < 49; r += 8) {
            float e0 = S[r * 49 + lane];
            float e1 = (lane < 17) ? S[r * 49 + 32 + lane] : -1e30f;
            float m = fmaxf(e0, e1);
            #pragma unroll
            for (int off = 16; off; off >>= 1)
                m = fmaxf(m, __shfl_xor_sync(0xffffffffu, m, off));
            float p0 = expf(e0 - m);
            float p1 = (lane < 17) ? expf(e1 - m) : 0.0f;
            float ssum = p0 + p1;
            #pragma unroll
            for (int off = 16; off; off >>= 1)
                ssum += __shfl_xor_sync(0xffffffffu, ssum, off);
            float invs = 1.0f / ssum;
            S[r * 49 + lane] = p0 * invs;
            if (lane < 17) S[r * 49 + 32 + lane] = p1 * invs;
        }
        __syncthreads();

        // AV: thread = (qi, d-pair)
        if (tid < 245) {
            int qi = tid / 5, dp = tid % 5;
            float ax = 0.0f, ay = 0.0f;
            #pragma unroll 7
            for (int kj = 0; kj < 49; kj++) {
                float a = S[qi * 49 + kj];
                float2 vv = *(const float2*)&vh[kj * 10 + dp * 2];
                ax = fmaf(a, vv.x, ax);
                ay = fmaf(a, vv.y, ay);
            }
            Osm[qi * 60 + h * 10 + dp * 2]     = ax;
            Osm[qi * 60 + h * 10 + dp * 2 + 1] = ay;
        }
        __syncthreads();
    }

    // ---- stage proj_w into (now free) QKV region ----
    float* Pw = QKV;
    {
        const float4* pg4 = (const float4*)proj_w;
        float4* ps4 = (float4*)Pw;
        for (int i = tid; i < 900; i += 256) ps4[i] = pg4[i];
    }
    __syncthreads();

    // ---- output projection + unpadded scatter ----
    if (tid < 245) {
        int t = tid / 5, j = tid % 5;
        int o0 = j * 12;
        float acc[12];
        #pragma unroll
        for (int jj = 0; jj < 12; jj++) acc[jj] = __ldg(proj_b + o0 + jj);
        #pragma unroll
        for (int c4 = 0; c4 < 15; c4++) {
            float4 xv = *(const float4*)&Osm[t * 60 + c4 * 4];
            #pragma unroll
            for (int jj = 0; jj < 12; jj++) {
                float4 wv = *(const float4*)&Pw[(o0 + jj) * 60 + c4 * 4];
                acc[jj] = fmaf(xv.x, wv.x, acc[jj]);
                acc[jj] = fmaf(xv.y, wv.y, acc[jj]);
                acc[jj] = fmaf(xv.z, wv.z, acc[jj]);
                acc[jj] = fmaf(xv.w, wv.w, acc[jj]);
            }
        }
        int r  = wi * 7 + t / 7;
        int cc = wj * 7 + t % 7;
        if (r < 64 && cc < 64) {
            float* og = out + ((b * 64 + r) * 64 + cc) * 60 + o0;
            #pragma unroll
            for (int q4 = 0; q4 < 3; q4++)
                *(float4*)&og[q4 * 4] = make_float4(acc[q4 * 4], acc[q4 * 4 + 1],
                                                    acc[q4 * 4 + 2], acc[q4 * 4 + 3]);
        }
    }
}

extern "C" void kernel_launch(void* const* d_in, const int* in_sizes, int n_in,
                              void* d_out, int out_size) {
    const float* x      = (const float*)d_in[0];
    const float* qkv_w  = (const float*)d_in[1];
    const float* qkv_b  = (const float*)d_in[2];
    const float* lscale = (const float*)d_in[3];
    const float* proj_w = (const float*)d_in[4];
    const float* proj_b = (const float*)d_in[5];
    float* out = (float*)d_out;

    const int smem_bytes = 25500 * 4;  // 102000 B dynamic smem
    cudaFuncSetAttribute(swin_win_attn_kernel,
                         cudaFuncAttributeMaxDynamicSharedMemorySize, smem_bytes);
    swin_win_attn_kernel<<<3200, 256, smem_bytes>>>(
        x, qkv_w, qkv_b, lscale, proj_w, proj_b, out);
}

// round 2
// speedup vs baseline: 1.4626x; 1.4626x over previous
#include <cuda_runtime.h>
#include <math.h>

#define LOG100 4.605170185988092f

// B=32, H=W=64, C=60, NH=6, HD=10, WS=7, T=49 tokens/window
// padded 70x70 -> nw=10 -> 100 windows/image -> 3200 windows
// Block: 320 threads, one window per CTA.

__global__ __launch_bounds__(320, 2) void swin_win_attn_kernel(
    const float* __restrict__ x,       // [32,64,64,60]
    const float* __restrict__ qkv_w,   // [180,60]
    const float* __restrict__ qkv_b,   // [180]
    const float* __restrict__ ls,      // [6]
    const float* __restrict__ proj_w,  // [60,60]
    const float* __restrict__ proj_b,  // [60]
    float* __restrict__ out)           // [32,64,64,60]
{
    extern __shared__ float smem[];
    float* Wsm = smem;            // 10800: qkv_w staged; later proj_w (3600)
    float* Xs  = smem + 10800;    // 2940: x window; later attention output Osm
    float* QKV = smem + 13740;    // 8820: q|k|v each [6][49][10]
    // total 22560 floats = 90240 B -> 2 CTAs/SM

    const int tid = threadIdx.x;
    const int w  = blockIdx.x;
    const int b  = w / 100;
    const int wi = (w % 100) / 10;
    const int wj = w % 10;

    // ---- stage qkv_w (vectorized) ----
    {
        const float4* wg4 = (const float4*)qkv_w;
        float4* ws4 = (float4*)Wsm;
        for (int i = tid; i < 2700; i += 320) ws4[i] = wg4[i];
    }

    // ---- load x window with zero padding (float4) ----
    for (int i = tid; i < 735; i += 320) {
        int t = i / 15, c4 = i % 15;
        int r  = wi * 7 + t / 7;
        int cc = wj * 7 + t % 7;
        float4 v = make_float4(0.f, 0.f, 0.f, 0.f);
        if (r < 64 && cc < 64)
            v = *(const float4*)&x[((b * 64 + r) * 64 + cc) * 60 + c4 * 4];
        *(float4*)&Xs[t * 60 + c4 * 4] = v;
    }
    __syncthreads();

    // ---- QKV projection: 49 tokens x 180 outputs, K=60 ----
    // tile: 7 tokens x 4 outputs -> 315 threads active
    if (tid < 315) {
        const int og = tid / 7, tg = tid % 7;
        const int t0 = tg * 7, o0 = og * 4;
        float acc[7][4];
        #pragma unroll
        for (int j = 0; j < 4; j++) {
            float bv = __ldg(qkv_b + o0 + j);
            #pragma unroll
            for (int i = 0; i < 7; i++) acc[i][j] = bv;
        }
        #pragma unroll
        for (int c4 = 0; c4 < 15; c4++) {
            float4 xv[7];
            #pragma unroll
            for (int i = 0; i < 7; i++)
                xv[i] = *(const float4*)&Xs[(t0 + i) * 60 + c4 * 4];
            #pragma unroll
            for (int j = 0; j < 4; j++) {
                float4 wv = *(const float4*)&Wsm[(o0 + j) * 60 + c4 * 4];
                #pragma unroll
                for (int i = 0; i < 7; i++) {
                    acc[i][j] = fmaf(xv[i].x, wv.x, acc[i][j]);
                    acc[i][j] = fmaf(xv[i].y, wv.y, acc[i][j]);
                    acc[i][j] = fmaf(xv[i].z, wv.z, acc[i][j]);
                    acc[i][j] = fmaf(xv[i].w, wv.w, acc[i][j]);
                }
            }
        }
        #pragma unroll
        for (int j = 0; j < 4; j++) {
            int o = o0 + j;
            int part = o / 60, hh = (o % 60) / 10, d = o % 10;
            float* dst = QKV + part * 2940 + hh * 490 + d;
            #pragma unroll
            for (int i = 0; i < 7; i++) dst[(t0 + i) * 10] = acc[i][j];
        }
    }
    __syncthreads();

    // ---- normalize q (fold exp-clamped logit scale) and k ----
    for (int idx = tid; idx < 588; idx += 320) {
        int part = idx / 294;
        int rem = idx % 294;
        int h = rem / 49, t = rem % 49;
        float* p = QKV + part * 2940 + h * 490 + t * 10;
        float ss = 0.0f;
        #pragma unroll
        for (int d = 0; d < 10; d++) ss = fmaf(p[d], p[d], ss);
        float inv = 1.0f / fmaxf(sqrtf(ss), 1e-12f);
        if (part == 0) inv *= __expf(fminf(__ldg(ls + h), LOG100));
        #pragma unroll
        for (int d = 0; d < 10; d++) p[d] *= inv;
    }
    __syncthreads();

    // ---- fused attention: one thread per (head, query row), online softmax ----
    float* Osm = Xs;   // reuse x-window region for [49][60] output
    if (tid < 294) {
        const int h = tid / 49, qi = tid % 49;
        const float* qh = QKV + h * 490 + qi * 10;
        const float* Kh = QKV + 2940 + h * 490;
        const float* Vh = QKV + 5880 + h * 490;

        float2 q[5];
        #pragma unroll
        for (int d = 0; d < 5; d++) q[d] = *(const float2*)&qh[d * 2];

        float m = -1e30f, l = 0.0f;
        float o[10];
        #pragma unroll
        for (int d = 0; d < 10; d++) o[d] = 0.0f;

        for (int kj = 0; kj < 49; kj++) {
            const float* kr = Kh + kj * 10;
            float s = 0.0f;
            #pragma unroll
            for (int d = 0; d < 5; d++) {
                float2 kv = *(const float2*)&kr[d * 2];
                s = fmaf(q[d].x, kv.x, s);
                s = fmaf(q[d].y, kv.y, s);
            }
            float mn = fmaxf(m, s);
            float c = __expf(m - mn);
            float p = __expf(s - mn);
            l = l * c + p;
            const float* vr = Vh + kj * 10;
            #pragma unroll
            for (int d = 0; d < 10; d++)
                o[d] = fmaf(o[d], c, p * vr[d]);
            m = mn;
        }
        float inv = 1.0f / l;
        float* od = Osm + qi * 60 + h * 10;
        #pragma unroll
        for (int d = 0; d < 10; d++) od[d] = o[d] * inv;
    } else {
        // idle attention threads stage proj_w into (now free) Wsm
        const float4* pg4 = (const float4*)proj_w;
        float4* ps4 = (float4*)Wsm;
        for (int i = tid - 294; i < 900; i += 26) ps4[i] = pg4[i];
    }
    __syncthreads();

    // ---- output projection + unpadded scatter ----
    if (tid < 245) {
        const int t = tid / 5, j = tid % 5;
        const int o0 = j * 12;
        float acc[12];
        #pragma unroll
        for (int jj = 0; jj < 12; jj++) acc[jj] = __ldg(proj_b + o0 + jj);
        #pragma unroll
        for (int c4 = 0; c4 < 15; c4++) {
            float4 xv = *(const float4*)&Osm[t * 60 + c4 * 4];
            #pragma unroll
            for (int jj = 0; jj < 12; jj++) {
                float4 wv = *(const float4*)&Wsm[(o0 + jj) * 60 + c4 * 4];
                acc[jj] = fmaf(xv.x, wv.x, acc[jj]);
                acc[jj] = fmaf(xv.y, wv.y, acc[jj]);
                acc[jj] = fmaf(xv.z, wv.z, acc[jj]);
                acc[jj] = fmaf(xv.w, wv.w, acc[jj]);
            }
        }
        int r  = wi * 7 + t / 7;
        int cc = wj * 7 + t % 7;
        if (r < 64 && cc < 64) {
            float* og = out + ((b * 64 + r) * 64 + cc) * 60 + o0;
            #pragma unroll
            for (int q4 = 0; q4 < 3; q4++)
                *(float4*)&og[q4 * 4] = make_float4(acc[q4 * 4], acc[q4 * 4 + 1],
                                                    acc[q4 * 4 + 2], acc[q4 * 4 + 3]);
        }
    }
}

extern "C" void kernel_launch(void* const* d_in, const int* in_sizes, int n_in,
                              void* d_out, int out_size) {
    const float* x      = (const float*)d_in[0];
    const float* qkv_w  = (const float*)d_in[1];
    const float* qkv_b  = (const float*)d_in[2];
    const float* lscale = (const float*)d_in[3];
    const float* proj_w = (const float*)d_in[4];
    const float* proj_b = (const float*)d_in[5];
    float* out = (float*)d_out;

    const int smem_bytes = 22560 * 4;  // 90240 B
    cudaFuncSetAttribute(swin_win_attn_kernel,
                         cudaFuncAttributeMaxDynamicSharedMemorySize, smem_bytes);
    swin_win_attn_kernel<<<3200, 320, smem_bytes>>>(
        x, qkv_w, qkv_b, lscale, proj_w, proj_b, out);
}

// round 3
// speedup vs baseline: 1.5454x; 1.0566x over previous
#include <cuda_runtime.h>
#include <math.h>

#define LOG100 4.605170185988092f

// B=32, H=W=64, C=60, NH=6, HD=10 (padded to 12), WS=7, T=49
// 3200 windows, one per CTA, 320 threads.

__device__ __forceinline__ unsigned long long pack2(float a, float b) {
    unsigned long long r;
    asm("mov.b64 %0, {%1, %2};" : "=l"(r) : "f"(a), "f"(b));
    return r;
}
__device__ __forceinline__ void unpack2(unsigned long long v, float& a, float& b) {
    asm("mov.b64 {%0, %1}, %2;" : "=f"(a), "=f"(b) : "l"(v));
}
__device__ __forceinline__ unsigned long long fma2(unsigned long long a,
                                                   unsigned long long b,
                                                   unsigned long long c) {
    unsigned long long r;
    asm("fma.rn.f32x2 %0, %1, %2, %3;" : "=l"(r) : "l"(a), "l"(b), "l"(c));
    return r;
}
__device__ __forceinline__ unsigned long long mul2(unsigned long long a,
                                                   unsigned long long b) {
    unsigned long long r;
    asm("mul.rn.f32x2 %0, %1, %2;" : "=l"(r) : "l"(a), "l"(b));
    return r;
}

__global__ __launch_bounds__(320, 2) void swin_win_attn_kernel(
    const float* __restrict__ x,       // [32,64,64,60]
    const float* __restrict__ qkv_w,   // [180,60]
    const float* __restrict__ qkv_b,   // [180]
    const float* __restrict__ ls,      // [6]
    const float* __restrict__ proj_w,  // [60,60]
    const float* __restrict__ proj_b,  // [60]
    float* __restrict__ out)           // [32,64,64,60]
{
    extern __shared__ float smem[];
    float* Wsm = smem;            // 10800: qkv_w; later proj_w (3600)
    float* Xs  = smem + 10800;    // 2940: x window; later Osm [49][60]
    float* QKV = smem + 13740;    // 10584: q|k|v each [6][49][12] (stride 12, padded)
    // total 24324 floats = 97296 B -> 2 CTAs/SM

    const int tid = threadIdx.x;
    const int w  = blockIdx.x;
    const int b  = w / 100;
    const int wi = (w % 100) / 10;
    const int wj = w % 10;

    // ---- phase A: stage qkv_w, zero QKV pads, load x window ----
    {
        const float4* wg4 = (const float4*)qkv_w;
        float4* ws4 = (float4*)Wsm;
        for (int i = tid; i < 2700; i += 320) ws4[i] = wg4[i];
        float4* z4 = (float4*)QKV;
        float4 zz = make_float4(0.f, 0.f, 0.f, 0.f);
        for (int i = tid; i < 2646; i += 320) z4[i] = zz;
    }
    for (int i = tid; i < 735; i += 320) {
        int t = i / 15, c4 = i % 15;
        int r  = wi * 7 + t / 7;
        int cc = wj * 7 + t % 7;
        float4 v = make_float4(0.f, 0.f, 0.f, 0.f);
        if (r < 64 && cc < 64)
            v = *(const float4*)&x[((b * 64 + r) * 64 + cc) * 60 + c4 * 4];
        *(float4*)&Xs[t * 60 + c4 * 4] = v;
    }
    __syncthreads();

    // ---- QKV projection: 49 tokens x 180 outputs, K=60 (7 tok x 4 out tiles) ----
    if (tid < 315) {
        const int og = tid / 7, tg = tid % 7;
        const int t0 = tg * 7, o0 = og * 4;
        float acc[7][4];
        #pragma unroll
        for (int j = 0; j < 4; j++) {
            float bv = __ldg(qkv_b + o0 + j);
            #pragma unroll
            for (int i = 0; i < 7; i++) acc[i][j] = bv;
        }
        #pragma unroll
        for (int c4 = 0; c4 < 15; c4++) {
            float4 xv[7];
            #pragma unroll
            for (int i = 0; i < 7; i++)
                xv[i] = *(const float4*)&Xs[(t0 + i) * 60 + c4 * 4];
            #pragma unroll
            for (int j = 0; j < 4; j++) {
                float4 wv = *(const float4*)&Wsm[(o0 + j) * 60 + c4 * 4];
                #pragma unroll
                for (int i = 0; i < 7; i++) {
                    acc[i][j] = fmaf(xv[i].x, wv.x, acc[i][j]);
                    acc[i][j] = fmaf(xv[i].y, wv.y, acc[i][j]);
                    acc[i][j] = fmaf(xv[i].z, wv.z, acc[i][j]);
                    acc[i][j] = fmaf(xv[i].w, wv.w, acc[i][j]);
                }
            }
        }
        #pragma unroll
        for (int j = 0; j < 4; j++) {
            int o = o0 + j;
            int part = o / 60, hh = (o % 60) / 10, d = o % 10;
            float* dst = QKV + part * 3528 + hh * 588 + d;
            #pragma unroll
            for (int i = 0; i < 7; i++) dst[(t0 + i) * 12] = acc[i][j];
        }
    }
    __syncthreads();

    // ---- normalize q (fold exp-clamped logit scale) and k, vectorized ----
    for (int idx = tid; idx < 588; idx += 320) {
        int part = idx / 294;
        int rem = idx % 294;
        int h = rem / 49, t = rem % 49;
        float* p = QKV + part * 3528 + h * 588 + t * 12;
        float4 a = *(float4*)p;
        float4 bq = *(float4*)(p + 4);
        float4 cq = *(float4*)(p + 8);
        float ss = a.x * a.x + a.y * a.y + a.z * a.z + a.w * a.w
                 + bq.x * bq.x + bq.y * bq.y + bq.z * bq.z + bq.w * bq.w
                 + cq.x * cq.x + cq.y * cq.y;
        float inv = rsqrtf(fmaxf(ss, 1e-24f));
        if (part == 0) inv *= __expf(fminf(__ldg(ls + h), LOG100));
        a.x *= inv; a.y *= inv; a.z *= inv; a.w *= inv;
        bq.x *= inv; bq.y *= inv; bq.z *= inv; bq.w *= inv;
        cq.x *= inv; cq.y *= inv;
        *(float4*)p = a;
        *(float4*)(p + 4) = bq;
        *(float4*)(p + 8) = cq;
    }
    __syncthreads();

    // ---- fused attention: thread per (head, query row), chunked online softmax ----
    float* Osm = Xs;
    if (tid < 294) {
        const int h = tid / 49, qi = tid % 49;
        const float* qh = QKV + h * 588 + qi * 12;
        const float* Kh = QKV + 3528 + h * 588;
        const float* Vh = QKV + 7056 + h * 588;

        ulonglong2 q01 = *(const ulonglong2*)(qh);
        ulonglong2 q23 = *(const ulonglong2*)(qh + 4);
        ulonglong2 q45 = *(const ulonglong2*)(qh + 8);
        unsigned long long qp0 = q01.x, qp1 = q01.y, qp2 = q23.x,
                           qp3 = q23.y, qp4 = q45.x;

        float m = -1e30f, l = 0.0f;
        unsigned long long o2[5];
        #pragma unroll
        for (int i = 0; i < 5; i++) o2[i] = 0ull;

        #pragma unroll 1
        for (int c0 = 0; c0 < 49; c0 += 7) {
            float s[7];
            #pragma unroll
            for (int j = 0; j < 7; j++) {
                const float* kr = Kh + (c0 + j) * 12;
                ulonglong2 k01 = *(const ulonglong2*)(kr);
                ulonglong2 k23 = *(const ulonglong2*)(kr + 4);
                ulonglong2 k45 = *(const ulonglong2*)(kr + 8);
                unsigned long long acc = mul2(qp0, k01.x);
                acc = fma2(qp1, k01.y, acc);
                acc = fma2(qp2, k23.x, acc);
                acc = fma2(qp3, k23.y, acc);
                acc = fma2(qp4, k45.x, acc);
                float lo, hi;
                unpack2(acc, lo, hi);
                s[j] = lo + hi;
            }
            float lm = s[0];
            #pragma unroll
            for (int j = 1; j < 7; j++) lm = fmaxf(lm, s[j]);
            float mn = fmaxf(m, lm);
            float c = __expf(m - mn);
            unsigned long long c2 = pack2(c, c);
            #pragma unroll
            for (int i = 0; i < 5; i++) o2[i] = mul2(o2[i], c2);
            float lsum = 0.0f;
            #pragma unroll
            for (int j = 0; j < 7; j++) {
                float p = __expf(s[j] - mn);
                lsum += p;
                unsigned long long pp = pack2(p, p);
                const float* vr = Vh + (c0 + j) * 12;
                ulonglong2 v01 = *(const ulonglong2*)(vr);
                ulonglong2 v23 = *(const ulonglong2*)(vr + 4);
                ulonglong2 v45 = *(const ulonglong2*)(vr + 8);
                o2[0] = fma2(pp, v01.x, o2[0]);
                o2[1] = fma2(pp, v01.y, o2[1]);
                o2[2] = fma2(pp, v23.x, o2[2]);
                o2[3] = fma2(pp, v23.y, o2[3]);
                o2[4] = fma2(pp, v45.x, o2[4]);
            }
            l = l * c + lsum;
            m = mn;
        }
        float inv = 1.0f / l;
        unsigned long long inv2 = pack2(inv, inv);
        float* od = Osm + qi * 60 + h * 10;
        #pragma unroll
        for (int i = 0; i < 5; i++) {
            unsigned long long r = mul2(o2[i], inv2);
            *(unsigned long long*)(od + i * 2) = r;
        }
    } else {
        // idle attention threads stage proj_w into (now free) Wsm
        const float4* pg4 = (const float4*)proj_w;
        float4* ps4 = (float4*)Wsm;
        for (int i = tid - 294; i < 900; i += 26) ps4[i] = pg4[i];
    }
    __syncthreads();

    // ---- output projection + unpadded scatter ----
    if (tid < 245) {
        const int t = tid / 5, j = tid % 5;
        const int o0 = j * 12;
        float acc[12];
        #pragma unroll
        for (int jj = 0; jj < 12; jj++) acc[jj] = __ldg(proj_b + o0 + jj);
        #pragma unroll
        for (int c4 = 0; c4 < 15; c4++) {
            float4 xv = *(const float4*)&Osm[t * 60 + c4 * 4];
            #pragma unroll
            for (int jj = 0; jj < 12; jj++) {
                float4 wv = *(const float4*)&Wsm[(o0 + jj) * 60 + c4 * 4];
                acc[jj] = fmaf(xv.x, wv.x, acc[jj]);
                acc[jj] = fmaf(xv.y, wv.y, acc[jj]);
                acc[jj] = fmaf(xv.z, wv.z, acc[jj]);
                acc[jj] = fmaf(xv.w, wv.w, acc[jj]);
            }
        }
        int r  = wi * 7 + t / 7;
        int cc = wj * 7 + t % 7;
        if (r < 64 && cc < 64) {
            float* og = out + ((b * 64 + r) * 64 + cc) * 60 + o0;
            #pragma unroll
            for (int q4 = 0; q4 < 3; q4++)
                *(float4*)&og[q4 * 4] = make_float4(acc[q4 * 4], acc[q4 * 4 + 1],
                                                    acc[q4 * 4 + 2], acc[q4 * 4 + 3]);
        }
    }
}

extern "C" void kernel_launch(void* const* d_in, const int* in_sizes, int n_in,
                              void* d_out, int out_size) {
    const float* x      = (const float*)d_in[0];
    const float* qkv_w  = (const float*)d_in[1];
    const float* qkv_b  = (const float*)d_in[2];
    const float* lscale = (const float*)d_in[3];
    const float* proj_w = (const float*)d_in[4];
    const float* proj_b = (const float*)d_in[5];
    float* out = (float*)d_out;

    const int smem_bytes = 24324 * 4;  // 97296 B
    cudaFuncSetAttribute(swin_win_attn_kernel,
                         cudaFuncAttributeMaxDynamicSharedMemorySize, smem_bytes);
    swin_win_attn_kernel<<<3200, 320, smem_bytes>>>(
        x, qkv_w, qkv_b, lscale, proj_w, proj_b, out);
}

// round 4
// speedup vs baseline: 2.1150x; 1.3685x over previous
#include <cuda_runtime.h>
#include <math.h>

#define LOG100 4.605170185988092f

// B=32, H=W=64, C=60, NH=6, HD=10, WS=7, T=49; 3200 windows, 1/CTA, 320 thr.
// Q: [6][49][12] (stride 12, pads unused). KV: [6][49][20] = k0..k9|v0..v9.

__device__ __forceinline__ unsigned long long pack2(float a, float b) {
    unsigned long long r;
    asm("mov.b64 %0, {%1, %2};" : "=l"(r) : "f"(a), "f"(b));
    return r;
}
__device__ __forceinline__ void unpack2(unsigned long long v, float& a, float& b) {
    asm("mov.b64 {%0, %1}, %2;" : "=f"(a), "=f"(b) : "l"(v));
}
__device__ __forceinline__ unsigned long long fma2(unsigned long long a,
                                                   unsigned long long b,
                                                   unsigned long long c) {
    unsigned long long r;
    asm("fma.rn.f32x2 %0, %1, %2, %3;" : "=l"(r) : "l"(a), "l"(b), "l"(c));
    return r;
}
__device__ __forceinline__ unsigned long long mul2(unsigned long long a,
                                                   unsigned long long b) {
    unsigned long long r;
    asm("mul.rn.f32x2 %0, %1, %2;" : "=l"(r) : "l"(a), "l"(b));
    return r;
}

__global__ __launch_bounds__(320, 2) void swin_win_attn_kernel(
    const float* __restrict__ x,       // [32,64,64,60]
    const float* __restrict__ qkv_w,   // [180,60]
    const float* __restrict__ qkv_b,   // [180]
    const float* __restrict__ ls,      // [6]
    const float* __restrict__ proj_w,  // [60,60]
    const float* __restrict__ proj_b,  // [60]
    float* __restrict__ out)           // [32,64,64,60]
{
    extern __shared__ float smem[];
    float* Wsm = smem;            // 10800: qkv_w; later proj_w (3600)
    float* Xs  = smem + 10800;    // 2940: x window; later Osm [49][60]
    float* Qs  = smem + 13740;    // 3528: q [6][49][12]
    float* KVs = smem + 17268;    // 5880: kv [6][49][20]
    // total 23148 floats = 92592 B -> 2 CTAs/SM

    const int tid = threadIdx.x;
    const int w  = blockIdx.x;
    const int b  = w / 100;
    const int wi = (w % 100) / 10;
    const int wj = w % 10;

    // ---- phase A: stage qkv_w, load x window ----
    {
        const float4* wg4 = (const float4*)qkv_w;
        float4* ws4 = (float4*)Wsm;
        for (int i = tid; i < 2700; i += 320) ws4[i] = wg4[i];
    }
    for (int i = tid; i < 735; i += 320) {
        int t = i / 15, c4 = i % 15;
        int r  = wi * 7 + t / 7;
        int cc = wj * 7 + t % 7;
        float4 v = make_float4(0.f, 0.f, 0.f, 0.f);
        if (r < 64 && cc < 64)
            v = *(const float4*)&x[((b * 64 + r) * 64 + cc) * 60 + c4 * 4];
        *(float4*)&Xs[t * 60 + c4 * 4] = v;
    }
    __syncthreads();

    // ---- QKV GEMM: 7 tokens x 6 outputs per thread, 210 threads ----
    if (tid < 210) {
        const int og = tid / 7, tg = tid % 7;
        const int t0 = tg * 7, o0 = og * 6;
        float acc[7][6];
        #pragma unroll
        for (int j = 0; j < 6; j++) {
            float bv = __ldg(qkv_b + o0 + j);
            #pragma unroll
            for (int i = 0; i < 7; i++) acc[i][j] = bv;
        }
        #pragma unroll
        for (int c4 = 0; c4 < 15; c4++) {
            float4 xv[7];
            #pragma unroll
            for (int i = 0; i < 7; i++)
                xv[i] = *(const float4*)&Xs[(t0 + i) * 60 + c4 * 4];
            #pragma unroll
            for (int j = 0; j < 6; j++) {
                float4 wv = *(const float4*)&Wsm[(o0 + j) * 60 + c4 * 4];
                #pragma unroll
                for (int i = 0; i < 7; i++) {
                    acc[i][j] = fmaf(xv[i].x, wv.x, acc[i][j]);
                    acc[i][j] = fmaf(xv[i].y, wv.y, acc[i][j]);
                    acc[i][j] = fmaf(xv[i].z, wv.z, acc[i][j]);
                    acc[i][j] = fmaf(xv[i].w, wv.w, acc[i][j]);
                }
            }
        }
        // scatter as aligned float2 pairs (o0 even, pairs never straddle rows)
        #pragma unroll
        for (int i = 0; i < 7; i++) {
            int t = t0 + i;
            #pragma unroll
            for (int j2 = 0; j2 < 3; j2++) {
                int o = o0 + 2 * j2;
                int part = o / 60, rem = o % 60;
                int hh = rem / 10, d = rem % 10;
                float* dst = (part == 0)
                    ? (Qs + hh * 588 + t * 12 + d)
                    : (KVs + hh * 980 + t * 20 + (part == 2 ? 10 : 0) + d);
                *(float2*)dst = make_float2(acc[i][2 * j2], acc[i][2 * j2 + 1]);
            }
        }
    }
    __syncthreads();

    // ---- normalize q (fold exp-clamped logit scale) and k ----
    for (int idx = tid; idx < 588; idx += 320) {
        int part = idx / 294;
        int rem = idx % 294;
        int h = rem / 49, t = rem % 49;
        float* p = (part == 0) ? (Qs + h * 588 + t * 12)
                               : (KVs + h * 980 + t * 20);
        float4 a = *(float4*)p;
        float4 bq = *(float4*)(p + 4);
        float2 cq = *(float2*)(p + 8);
        float ss = a.x * a.x + a.y * a.y + a.z * a.z + a.w * a.w
                 + bq.x * bq.x + bq.y * bq.y + bq.z * bq.z + bq.w * bq.w
                 + cq.x * cq.x + cq.y * cq.y;
        float inv = rsqrtf(fmaxf(ss, 1e-24f));
        if (part == 0) inv *= __expf(fminf(__ldg(ls + h), LOG100));
        a.x *= inv; a.y *= inv; a.z *= inv; a.w *= inv;
        bq.x *= inv; bq.y *= inv; bq.z *= inv; bq.w *= inv;
        cq.x *= inv; cq.y *= inv;
        *(float4*)p = a;
        *(float4*)(p + 4) = bq;
        *(float2*)(p + 8) = cq;
    }
    __syncthreads();

    // ---- fused attention: 2 query rows per thread, chunked online softmax ----
    float* Osm = Xs;
    if (tid < 150) {
        const int h = tid / 25, ii = tid % 25;
        const int r0 = 2 * ii;
        const bool two = (ii < 24);

        const float* qp = Qs + h * 588 + r0 * 12;   // rows r0, r0+1 contiguous
        ulonglong2 Aq = *(const ulonglong2*)(qp);
        ulonglong2 Bq = *(const ulonglong2*)(qp + 4);
        ulonglong2 Cq = *(const ulonglong2*)(qp + 8);
        ulonglong2 Dq = *(const ulonglong2*)(qp + 12);
        ulonglong2 Eq = *(const ulonglong2*)(qp + 16);
        ulonglong2 Fq = *(const ulonglong2*)(qp + 20);
        const unsigned long long q00 = Aq.x, q01 = Aq.y, q02 = Bq.x,
                                 q03 = Bq.y, q04 = Cq.x;
        const unsigned long long q10 = Dq.x, q11 = Dq.y, q12 = Eq.x,
                                 q13 = Eq.y, q14 = Fq.x;

        unsigned long long o20[5], o21[5];
        #pragma unroll
        for (int i = 0; i < 5; i++) { o20[i] = 0ull; o21[i] = 0ull; }
        float m0 = -1e30f, l0 = 0.0f, m1 = -1e30f, l1 = 0.0f;

        const float* KVh = KVs + h * 980;

        #pragma unroll 1
        for (int c0 = 0; c0 < 49; c0 += 7) {
            float s0[7], s1[7];
            unsigned long long v01[7];
            #pragma unroll
            for (int j = 0; j < 7; j++) {
                const float* kr = KVh + (c0 + j) * 20;
                ulonglong2 K0 = *(const ulonglong2*)(kr);      // k0..k3
                ulonglong2 K1 = *(const ulonglong2*)(kr + 4);  // k4..k7
                ulonglong2 K2 = *(const ulonglong2*)(kr + 8);  // k8,k9 | v0,v1
                unsigned long long a0 = mul2(q00, K0.x);
                a0 = fma2(q01, K0.y, a0);
                a0 = fma2(q02, K1.x, a0);
                a0 = fma2(q03, K1.y, a0);
                a0 = fma2(q04, K2.x, a0);
                float lo, hi;
                unpack2(a0, lo, hi);
                s0[j] = lo + hi;
                unsigned long long a1 = mul2(q10, K0.x);
                a1 = fma2(q11, K0.y, a1);
                a1 = fma2(q12, K1.x, a1);
                a1 = fma2(q13, K1.y, a1);
                a1 = fma2(q14, K2.x, a1);
                unpack2(a1, lo, hi);
                s1[j] = lo + hi;
                v01[j] = K2.y;
            }
            float lm0 = s0[0], lm1 = s1[0];
            #pragma unroll
            for (int j = 1; j < 7; j++) {
                lm0 = fmaxf(lm0, s0[j]);
                lm1 = fmaxf(lm1, s1[j]);
            }
            float mn0 = fmaxf(m0, lm0), mn1 = fmaxf(m1, lm1);
            float cf0 = __expf(m0 - mn0), cf1 = __expf(m1 - mn1);
            unsigned long long c20 = pack2(cf0, cf0), c21 = pack2(cf1, cf1);
            #pragma unroll
            for (int i = 0; i < 5; i++) {
                o20[i] = mul2(o20[i], c20);
                o21[i] = mul2(o21[i], c21);
            }
            float ls0 = 0.0f, ls1 = 0.0f;
            #pragma unroll
            for (int j = 0; j < 7; j++) {
                float p0 = __expf(s0[j] - mn0);
                float p1 = __expf(s1[j] - mn1);
                ls0 += p0; ls1 += p1;
                unsigned long long pp0 = pack2(p0, p0);
                unsigned long long pp1 = pack2(p1, p1);
                const float* kr = KVh + (c0 + j) * 20;
                ulonglong2 V1 = *(const ulonglong2*)(kr + 12);  // v2..v5
                ulonglong2 V2 = *(const ulonglong2*)(kr + 16);  // v6..v9
                o20[0] = fma2(pp0, v01[j], o20[0]);
                o20[1] = fma2(pp0, V1.x, o20[1]);
                o20[2] = fma2(pp0, V1.y, o20[2]);
                o20[3] = fma2(pp0, V2.x, o20[3]);
                o20[4] = fma2(pp0, V2.y, o20[4]);
                o21[0] = fma2(pp1, v01[j], o21[0]);
                o21[1] = fma2(pp1, V1.x, o21[1]);
                o21[2] = fma2(pp1, V1.y, o21[2]);
                o21[3] = fma2(pp1, V2.x, o21[3]);
                o21[4] = fma2(pp1, V2.y, o21[4]);
            }
            l0 = l0 * cf0 + ls0; m0 = mn0;
            l1 = l1 * cf1 + ls1; m1 = mn1;
        }
        {
            float inv0 = 1.0f / l0;
            unsigned long long i20 = pack2(inv0, inv0);
            float* od = Osm + r0 * 60 + h * 10;
            #pragma unroll
            for (int i = 0; i < 5; i++)
                *(unsigned long long*)(od + 2 * i) = mul2(o20[i], i20);
        }
        if (two) {
            float inv1 = 1.0f / l1;
            unsigned long long i21 = pack2(inv1, inv1);
            float* od = Osm + (r0 + 1) * 60 + h * 10;
            #pragma unroll
            for (int i = 0; i < 5; i++)
                *(unsigned long long*)(od + 2 * i) = mul2(o21[i], i21);
        }
    } else if (tid >= 160) {
        // stage proj_w into (now free) Wsm
        const float4* pg4 = (const float4*)proj_w;
        float4* ps4 = (float4*)Wsm;
        for (int i = tid - 160; i < 900; i += 160) ps4[i] = pg4[i];
    }
    __syncthreads();

    // ---- output projection: 7 tokens x 6 outputs per thread, 70 threads ----
    if (tid < 70) {
        const int tg = tid / 10, jg = tid % 10;
        const int t0 = tg * 7, o0 = jg * 6;
        float acc[7][6];
        #pragma unroll
        for (int j = 0; j < 6; j++) {
            float bv = __ldg(proj_b + o0 + j);
            #pragma unroll
            for (int i = 0; i < 7; i++) acc[i][j] = bv;
        }
        #pragma unroll
        for (int c4 = 0; c4 < 15; c4++) {
            float4 xv[7];
            #pragma unroll
            for (int i = 0; i < 7; i++)
                xv[i] = *(const float4*)&Osm[(t0 + i) * 60 + c4 * 4];
            #pragma unroll
            for (int j = 0; j < 6; j++) {
                float4 wv = *(const float4*)&Wsm[(o0 + j) * 60 + c4 * 4];
                #pragma unroll
                for (int i = 0; i < 7; i++) {
                    acc[i][j] = fmaf(xv[i].x, wv.x, acc[i][j]);
                    acc[i][j] = fmaf(xv[i].y, wv.y, acc[i][j]);
                    acc[i][j] = fmaf(xv[i].z, wv.z, acc[i][j]);
                    acc[i][j] = fmaf(xv[i].w, wv.w, acc[i][j]);
                }
            }
        }
        #pragma unroll
        for (int i = 0; i < 7; i++) {
            int t = t0 + i;
            int r  = wi * 7 + t / 7;
            int cc = wj * 7 + t % 7;
            if (r < 64 && cc < 64) {
                float* og = out + ((b * 64 + r) * 64 + cc) * 60 + o0;
                *(float2*)(og)     = make_float2(acc[i][0], acc[i][1]);
                *(float2*)(og + 2) = make_float2(acc[i][2], acc[i][3]);
                *(float2*)(og + 4) = make_float2(acc[i][4], acc[i][5]);
            }
        }
    }
}

extern "C" void kernel_launch(void* const* d_in, const int* in_sizes, int n_in,
                              void* d_out, int out_size) {
    const float* x      = (const float*)d_in[0];
    const float* qkv_w  = (const float*)d_in[1];
    const float* qkv_b  = (const float*)d_in[2];
    const float* lscale = (const float*)d_in[3];
    const float* proj_w = (const float*)d_in[4];
    const float* proj_b = (const float*)d_in[5];
    float* out = (float*)d_out;

    const int smem_bytes = 23148 * 4;  // 92592 B
    cudaFuncSetAttribute(swin_win_attn_kernel,
                         cudaFuncAttributeMaxDynamicSharedMemorySize, smem_bytes);
    swin_win_attn_kernel<<<3200, 320, smem_bytes>>>(
        x, qkv_w, qkv_b, lscale, proj_w, proj_b, out);
}